// round 11
// baseline (speedup 1.0000x reference)
#include <cuda_runtime.h>
#include <math.h>
#include <stdint.h>

#define BATCH 32
#define DIM   256
#define HGT   32
#define WID   42
#define HW    1344          // 32*42
#define EPS_BN 1e-5f

// ---------------- scratch (device globals; no allocation allowed) -------------
__device__ float g_nrm0[BATCH * HW];
__device__ float g_nrm1[BATCH * HW];
__device__ float g_vn0[(size_t)BATCH * DIM * HW];     // normalized volumes (fp32)
__device__ float g_vn1[(size_t)BATCH * DIM * HW];
__device__ float g_corr[(size_t)BATCH * HW * HW];     // 231 MB
__device__ int   g_inds[BATCH * HW];
__device__ float g_val [BATCH * HW];
__device__ float g_A1[(size_t)BATCH * 517 * HW];      // relu(bn1(feat_agg))
__device__ float g_S1[BATCH * 256 * 336];
__device__ float g_C1[BATCH * 256 * 336];
__device__ float g_X1[BATCH * 256 * 336];
__device__ float g_S2[BATCH * 128 * 88];
__device__ float g_C2[BATCH * 128 * 88];
__device__ float g_X2[BATCH * 128 * 88];
__device__ float g_Y [BATCH * 1408];

// ---------------- 1a) column norms --------------------------------------------
__global__ void norm_kernel(const float* __restrict__ vol, float* __restrict__ nrm)
{
    int i = blockIdx.x * blockDim.x + threadIdx.x;
    if (i >= BATCH * HW) return;
    int b = i / HW, m = i - b * HW;
    const float* p = vol + (size_t)b * DIM * HW + m;
    float s = 0.f;
    for (int d = 0; d < DIM; d++) {
        float v = p[(size_t)d * HW];
        float sq = __fmul_rn(v, v);
        s = __fadd_rn(s, sq);
    }
    nrm[i] = fmaxf(__fsqrt_rn(s), 1e-12f);
}

// ---------------- 1b) normalized volume: vn = v / norm (IEEE div) --------------
__global__ void normscale_kernel(const float* __restrict__ vol,
                                 const float* __restrict__ nrm,
                                 float* __restrict__ vn)
{
    int i = blockIdx.x * blockDim.x + threadIdx.x;
    if (i >= BATCH * DIM * HW) return;
    int b = i / (DIM * HW);
    int p = i % HW;
    vn[i] = __fdiv_rn(vol[i], nrm[b * HW + p]);
}

// ---------------- 2) corr[b,m,n] = vn0[:,m] . vn1[:,n] ------------------------
// 128x128x8 tiles, 256 threads, 8x8 microtile, k-ascending single-FMA acc.
__global__ __launch_bounds__(256) void corr_kernel(
    const float* __restrict__ v0, const float* __restrict__ v1,
    float* __restrict__ corr)
{
    const int b  = blockIdx.z;
    const int m0 = blockIdx.y * 128;
    const int n0 = blockIdx.x * 128;
    const float* A  = v0 + (size_t)b * DIM * HW;   // (D, HW)
    const float* Bv = v1 + (size_t)b * DIM * HW;

    __shared__ float As[8][128];
    __shared__ float Bs[8][128];

    const int tid = threadIdx.x;
    const int tx = tid & 15, ty = tid >> 4;

    float acc[8][8] = {};

    for (int k0 = 0; k0 < DIM; k0 += 8) {
#pragma unroll
        for (int i = 0; i < 4; i++) {
            int idx = tid + i * 256;
            int k = idx >> 7, m = idx & 127;
            int gm = m0 + m;
            As[k][m] = (gm < HW) ? A [(size_t)(k0 + k) * HW + gm] : 0.f;
            int gn = n0 + m;
            Bs[k][m] = (gn < HW) ? Bv[(size_t)(k0 + k) * HW + gn] : 0.f;
        }
        __syncthreads();
#pragma unroll
        for (int k = 0; k < 8; k++) {
            float ra[8], rb[8];
#pragma unroll
            for (int i = 0; i < 8; i++) ra[i] = As[k][ty * 8 + i];
#pragma unroll
            for (int j = 0; j < 8; j++) rb[j] = Bs[k][tx * 8 + j];
#pragma unroll
            for (int i = 0; i < 8; i++)
#pragma unroll
                for (int j = 0; j < 8; j++)
                    acc[i][j] = fmaf(ra[i], rb[j], acc[i][j]);
        }
        __syncthreads();
    }

#pragma unroll
    for (int i = 0; i < 8; i++) {
        int gm = m0 + ty * 8 + i;
        if (gm >= HW) continue;
        size_t base = ((size_t)b * HW + gm) * HW;
#pragma unroll
        for (int j = 0; j < 8; j++) {
            int gn = n0 + tx * 8 + j;
            if (gn < HW) corr[base + gn] = acc[i][j];
        }
    }
}

// ---------------- 3) per-row softmax -> argmax(prob) + max(prob) --------------
// REPLICATES the reference's fp32 tie semantics: prob_i = exp(x_i - max) / sum,
// argmax over prob with FIRST-index tie-break (jnp.argmax). Ties arise when
// expf rounds to 1.0 near the max, or the division rounds onto pmax = 1/sum.
// max(prob) is always fdiv(1, sum) (division monotone in numerator).
__global__ __launch_bounds__(256) void row_softmax_kernel(
    const float* __restrict__ corr, int* __restrict__ inds, float* __restrict__ val)
{
    __shared__ float s[HW];
    __shared__ float red[256];
    __shared__ int   redi[256];
    const size_t row = blockIdx.x;
    const float* cr = corr + row * HW;
    const int tid = threadIdx.x;

    for (int i = tid; i < HW; i += 256) s[i] = cr[i];
    __syncthreads();

    // pass 1: row max (value only)
    float mx = -3.4e38f;
    for (int i = tid; i < HW; i += 256) mx = fmaxf(mx, s[i]);
    red[tid] = mx;
    __syncthreads();
    for (int off = 128; off; off >>= 1) {
        if (tid < off) red[tid] = fmaxf(red[tid], red[tid + off]);
        __syncthreads();
    }
    mx = red[0];
    __syncthreads();

    // pass 2: e_i = exp(x_i - mx) stored in-place; partial sums.
    // (each s[i] is read/written only by the thread owning stride class i%256)
    float sum = 0.f;
    for (int i = tid; i < HW; i += 256) {
        float e = expf(__fadd_rn(s[i], -mx));
        s[i] = e;
        sum = __fadd_rn(sum, e);
    }
    red[tid] = sum;
    __syncthreads();
    for (int off = 128; off; off >>= 1) {
        if (tid < off) red[tid] = __fadd_rn(red[tid], red[tid + off]);
        __syncthreads();
    }
    sum = red[0];
    const float pmax = __fdiv_rn(1.f, sum);

    // pass 3: first index whose prob equals pmax
    int best = 0x7fffffff;
    for (int i = tid; i < HW; i += 256) {
        if (__fdiv_rn(s[i], sum) == pmax && i < best) best = i;
    }
    redi[tid] = best;
    __syncthreads();
    for (int off = 128; off; off >>= 1) {
        if (tid < off) redi[tid] = min(redi[tid], redi[tid + off]);
        __syncthreads();
    }
    if (tid == 0) { inds[row] = redi[0]; val[row] = pmax; }
}

// ---------------- 4) build feat_agg = relu(bn1(agg)) --------------------------
// channels: [0,256) feat1 | 256 gx | 257 gy | [258,514) feat2 warped | 514 wx | 515 wy | 516 val
__global__ void build_agg_kernel(
    const float* __restrict__ f1, const float* __restrict__ f2,
    const int* __restrict__ inds, const float* __restrict__ val,
    const float* __restrict__ bnG, const float* __restrict__ bnB,
    float* __restrict__ A1)
{
    const int p = blockIdx.x * blockDim.x + threadIdx.x;
    if (p >= HW) return;
    const int c = blockIdx.y;
    const int b = blockIdx.z;
    const float sc = __fdiv_rn(bnG[c], __fsqrt_rn(1.f + EPS_BN));
    const float sh = bnB[c];

    float x;
    if (c < 256) {
        x = f1[((size_t)b * 256 + c) * HW + p];
    } else if (c == 256) {
        x = (float)(p % WID);
    } else if (c == 257) {
        x = (float)(p / WID);
    } else if (c < 514) {
        int ind = inds[b * HW + p];
        x = f2[((size_t)b * 256 + (c - 258)) * HW + ind];
    } else if (c == 514) {
        x = (float)(inds[b * HW + p] % WID);
    } else if (c == 515) {
        x = (float)(inds[b * HW + p] / WID);
    } else {
        x = val[b * HW + p];
    }
    A1[((size_t)b * 517 + c) * HW + p] = fmaxf(__fadd_rn(__fmul_rn(x, sc), sh), 0.f);
}

// ---------------- 5) generic implicit-GEMM conv (fp32) ------------------------
// out = sum act(in) * w  (+ add) (+ bias); act = relu(bn(x)) if bnG != null.
// M=Cout, N=B*OH*OW (multiple of 64 here), K=Cin*KH*KH. 64x64x8 tiles.
template <int KH, int STRIDE, int PAD>
__global__ __launch_bounds__(256) void conv_kernel(
    const float* __restrict__ in, const float* __restrict__ wgt,
    const float* __restrict__ bnG, const float* __restrict__ bnB,
    const float* __restrict__ add, const float* __restrict__ bias,
    float* __restrict__ out,
    int Cin, int Cout, int IH, int IW, int OH, int OW)
{
    const int KK  = KH * KH;
    const int K   = Cin * KK;
    const int OHW = OH * OW;
    const int IHW = IH * IW;

    __shared__ float As[8][65];
    __shared__ float Bs[8][68];

    const int tid = threadIdx.x;
    const int tx = tid & 15, ty = tid >> 4;
    const int m0 = blockIdx.y * 64, n0 = blockIdx.x * 64;

    const int lbn = tid & 63;
    const int lbk0 = tid >> 6;               // 0..3
    const int gn = n0 + lbn;
    const int nb = gn / OHW;
    const int pp = gn - nb * OHW;
    const int oh = pp / OW;
    const int ow = pp - oh * OW;
    const int ihb = oh * STRIDE - PAD;
    const int iwb = ow * STRIDE - PAD;
    const float* inb = in + (size_t)nb * Cin * IHW;
    const bool do_act = (bnG != nullptr);
    const float bden = __fsqrt_rn(1.f + EPS_BN);

    float acc[4][4] = {};
    const int nIter = (K + 7) >> 3;

    for (int it = 0; it < nIter; ++it) {
        const int k0 = it << 3;
#pragma unroll
        for (int i = 0; i < 2; i++) {
            int idx = tid + i * 256;
            int m = idx >> 3, k = idx & 7;
            int gm = m0 + m, gk = k0 + k;
            As[k][m] = (gm < Cout && gk < K) ? wgt[(size_t)gm * K + gk] : 0.f;
        }
#pragma unroll
        for (int r = 0; r < 2; r++) {
            int k = lbk0 + r * 4;
            int gk = k0 + k;
            float x = 0.f;
            if (gk < K) {
                int ci, kh, kw;
                if (KK == 1) { ci = gk; kh = 0; kw = 0; }
                else { ci = gk / KK; int rr = gk - ci * KK; kh = rr / KH; kw = rr - kh * KH; }
                int ih = ihb + kh, iw = iwb + kw;
                if (ih >= 0 && ih < IH && iw >= 0 && iw < IW) {
                    x = inb[(size_t)ci * IHW + ih * IW + iw];
                    if (do_act) {
                        float sc = __fdiv_rn(bnG[ci], bden);
                        x = fmaxf(__fadd_rn(__fmul_rn(x, sc), bnB[ci]), 0.f);
                    }
                }
            }
            Bs[k][lbn] = x;
        }
        __syncthreads();
#pragma unroll
        for (int k = 0; k < 8; k++) {
            float ra[4], rb[4];
#pragma unroll
            for (int i = 0; i < 4; i++) ra[i] = As[k][ty * 4 + i];
#pragma unroll
            for (int j = 0; j < 4; j++) rb[j] = Bs[k][tx * 4 + j];
#pragma unroll
            for (int i = 0; i < 4; i++)
#pragma unroll
                for (int j = 0; j < 4; j++)
                    acc[i][j] = fmaf(ra[i], rb[j], acc[i][j]);
        }
        __syncthreads();
    }

#pragma unroll
    for (int j = 0; j < 4; j++) {
        int gnn = n0 + tx * 4 + j;
        int nb2 = gnn / OHW;
        int p2  = gnn - nb2 * OHW;
#pragma unroll
        for (int i = 0; i < 4; i++) {
            int gm = m0 + ty * 4 + i;
            if (gm < Cout) {
                size_t oidx = ((size_t)nb2 * Cout + gm) * OHW + p2;
                float v = acc[i][j];
                if (add)  v = __fadd_rn(v, add[oidx]);
                if (bias) v = __fadd_rn(v, bias[gm]);
                out[oidx] = v;
            }
        }
    }
}

// ---------------- 6) head MLP + quaternion-to-matrix --------------------------
__global__ __launch_bounds__(128) void head_kernel(
    const float* __restrict__ Y,
    const float* __restrict__ W1, const float* __restrict__ b1,
    const float* __restrict__ W2, const float* __restrict__ b2,
    float* __restrict__ out)
{
    __shared__ float v[1408];
    __shared__ float h[128];
    __shared__ float pr[7];
    const int b = blockIdx.x;
    const int tid = threadIdx.x;

    for (int i = tid; i < 1408; i += 128) v[i] = Y[b * 1408 + i];
    __syncthreads();

    float s = 0.f;
    const float* wr = W1 + (size_t)tid * 1408;
    for (int k = 0; k < 1408; k++) s = fmaf(v[k], wr[k], s);
    h[tid] = fmaxf(__fadd_rn(s, b1[tid]), 0.f);
    __syncthreads();

    if (tid < 7) {
        float s2 = 0.f;
        const float* w2 = W2 + tid * 128;
        for (int k = 0; k < 128; k++) s2 = fmaf(h[k], w2[k], s2);
        pr[tid] = __fadd_rn(s2, b2[tid]);
    }
    __syncthreads();

    if (tid == 0) {
        float r = pr[0], i = pr[1], j = pr[2], k = pr[3];
        float two_s = __fdiv_rn(2.f, (r * r + i * i + j * j + k * k));
        float* R = out + b * 9;
        R[0] = 1.f - two_s * (j * j + k * k);
        R[1] = two_s * (i * j - k * r);
        R[2] = two_s * (i * k + j * r);
        R[3] = two_s * (i * j + k * r);
        R[4] = 1.f - two_s * (i * i + k * k);
        R[5] = two_s * (j * k - i * r);
        R[6] = two_s * (i * k - j * r);
        R[7] = two_s * (j * k + i * r);
        R[8] = 1.f - two_s * (i * i + j * j);
        float* T = out + BATCH * 9 + b * 3;
        T[0] = pr[4]; T[1] = pr[5]; T[2] = pr[6];
    }
}

// ---------------- launch ------------------------------------------------------
extern "C" void kernel_launch(void* const* d_in, const int* in_sizes, int n_in,
                              void* d_out, int out_size)
{
    const float* feat1      = (const float*)d_in[0];
    const float* feat2      = (const float*)d_in[1];
    const float* b1_bn1_g   = (const float*)d_in[2];
    const float* b1_bn1_b   = (const float*)d_in[3];
    const float* b1_conv1_w = (const float*)d_in[4];
    const float* b1_bn2_g   = (const float*)d_in[5];
    const float* b1_bn2_b   = (const float*)d_in[6];
    const float* b1_conv2_w = (const float*)d_in[7];
    const float* b1_sc_w    = (const float*)d_in[8];
    const float* b2_bn1_g   = (const float*)d_in[9];
    const float* b2_bn1_b   = (const float*)d_in[10];
    const float* b2_conv1_w = (const float*)d_in[11];
    const float* b2_bn2_g   = (const float*)d_in[12];
    const float* b2_bn2_b   = (const float*)d_in[13];
    const float* b2_conv2_w = (const float*)d_in[14];
    const float* b2_sc_w    = (const float*)d_in[15];
    const float* bn3_g      = (const float*)d_in[16];
    const float* bn3_b      = (const float*)d_in[17];
    const float* conv3_w    = (const float*)d_in[18];
    const float* conv3_b    = (const float*)d_in[19];
    const float* head_w1    = (const float*)d_in[20];
    const float* head_b1    = (const float*)d_in[21];
    const float* head_w2    = (const float*)d_in[22];
    const float* head_b2    = (const float*)d_in[23];
    float* out = (float*)d_out;

    float *nrm0, *nrm1, *vn0, *vn1, *corr, *val, *A1, *S1, *C1, *X1, *S2, *C2, *X2, *Y;
    int* inds;
    cudaGetSymbolAddress((void**)&nrm0, g_nrm0);
    cudaGetSymbolAddress((void**)&nrm1, g_nrm1);
    cudaGetSymbolAddress((void**)&vn0,  g_vn0);
    cudaGetSymbolAddress((void**)&vn1,  g_vn1);
    cudaGetSymbolAddress((void**)&corr, g_corr);
    cudaGetSymbolAddress((void**)&inds, g_inds);
    cudaGetSymbolAddress((void**)&val,  g_val);
    cudaGetSymbolAddress((void**)&A1,   g_A1);
    cudaGetSymbolAddress((void**)&S1,   g_S1);
    cudaGetSymbolAddress((void**)&C1,   g_C1);
    cudaGetSymbolAddress((void**)&X1,   g_X1);
    cudaGetSymbolAddress((void**)&S2,   g_S2);
    cudaGetSymbolAddress((void**)&C2,   g_C2);
    cudaGetSymbolAddress((void**)&X2,   g_X2);
    cudaGetSymbolAddress((void**)&Y,    g_Y);

    // 1) norms + normalized volumes
    norm_kernel<<<(BATCH * HW + 255) / 256, 256>>>(feat1, nrm0);
    norm_kernel<<<(BATCH * HW + 255) / 256, 256>>>(feat2, nrm1);
    {
        int n = BATCH * DIM * HW;
        normscale_kernel<<<(n + 255) / 256, 256>>>(feat1, nrm0, vn0);
        normscale_kernel<<<(n + 255) / 256, 256>>>(feat2, nrm1, vn1);
    }

    // 2) correlation volume
    {
        dim3 grid((HW + 127) / 128, (HW + 127) / 128, BATCH);
        corr_kernel<<<grid, 256>>>(vn0, vn1, corr);
    }

    // 3) per-row softmax argmax (prob-space, first-index ties) + max prob
    row_softmax_kernel<<<BATCH * HW, 256>>>(corr, inds, val);

    // 4) feat_agg (pre-activated with bn1 of block1)
    {
        dim3 grid((HW + 255) / 256, 517, BATCH);
        build_agg_kernel<<<grid, 256>>>(feat1, feat2, inds, val, b1_bn1_g, b1_bn1_b, A1);
    }

    // 5) block 1 (517 -> 256, spatial 32x42 -> 16x21)
    {
        int N1 = BATCH * 16 * 21;   // 10752
        conv_kernel<1, 2, 0><<<dim3(N1 / 64, 4), 256>>>(A1, b1_sc_w,    nullptr, nullptr, nullptr, nullptr, S1, 517, 256, 32, 42, 16, 21);
        conv_kernel<3, 2, 1><<<dim3(N1 / 64, 4), 256>>>(A1, b1_conv1_w, nullptr, nullptr, nullptr, nullptr, C1, 517, 256, 32, 42, 16, 21);
        conv_kernel<3, 1, 1><<<dim3(N1 / 64, 4), 256>>>(C1, b1_conv2_w, b1_bn2_g, b1_bn2_b, S1, nullptr, X1, 256, 256, 16, 21, 16, 21);
    }

    // 6) block 2 (256 -> 128, spatial 16x21 -> 8x11); bn1 of block2 fused into loads
    {
        int N2 = BATCH * 8 * 11;    // 2816
        conv_kernel<1, 2, 0><<<dim3(N2 / 64, 2), 256>>>(X1, b2_sc_w,    b2_bn1_g, b2_bn1_b, nullptr, nullptr, S2, 256, 128, 16, 21, 8, 11);
        conv_kernel<3, 2, 1><<<dim3(N2 / 64, 2), 256>>>(X1, b2_conv1_w, b2_bn1_g, b2_bn1_b, nullptr, nullptr, C2, 256, 128, 16, 21, 8, 11);
        conv_kernel<3, 1, 1><<<dim3(N2 / 64, 2), 256>>>(C2, b2_conv2_w, b2_bn2_g, b2_bn2_b, S2, nullptr, X2, 128, 128, 8, 11, 8, 11);
        conv_kernel<1, 1, 0><<<dim3(N2 / 64, 1), 256>>>(X2, conv3_w, bn3_g, bn3_b, nullptr, conv3_b, Y, 128, 16, 8, 11, 8, 11);
    }

    // 7) head + quaternion
    head_kernel<<<BATCH, 128>>>(Y, head_w1, head_b1, head_w2, head_b2, out);
}